// round 15
// baseline (speedup 1.0000x reference)
#include <cuda_runtime.h>
#include <cuda_bf16.h>
#include <math.h>
#include <stdint.h>

#define NB 48
#define NC 768
#define NS 361
#define NT 64
#define SPAD 384
#define ND2 (NC / 2)
#define NS2 (SPAD / 2)
#define NPAIR (NB * NB)

#define TEMP1 4.0f
#define TEMP2 5.0f
#define TEMP3 10.0f
#define EPSV  1e-8f

typedef unsigned long long ull;

// ================= device scratch =================
__device__ float g_ctxp[(size_t)NB * NC * SPAD];      // padded ctx (gram input)
__device__ uint32_t g_ctxPH[(size_t)NB * ND2 * SPAD]; // bf16x2 hi ctx [b][d2][s]
__device__ uint32_t g_ctxPL[(size_t)NB * ND2 * SPAD];
__device__ uint32_t g_wPH[(size_t)NB * ND2 * NT];     // bf16x2 hi words [c][d2][t]
__device__ uint32_t g_wPL[(size_t)NB * ND2 * NT];
__device__ uint32_t g_GPH[(size_t)NB * NS2 * SPAD];   // bf16x2 hi G [b][k2][s]
__device__ uint32_t g_GPL[(size_t)NB * NS2 * SPAD];
__device__ float g_a2uD[(size_t)NB * SPAD * NT];      // fp32 a2u, diagonal pairs only
__device__ float g_cols[NPAIR * NT];
__device__ float g_w12[NPAIR * NT];
__device__ float g_w2[NPAIR * NT];
__device__ float g_w1n[NB * NT];
__device__ float g_gn[NB];
__device__ float g_sn[NB];
__device__ float g_sc0[NB * NB];
__device__ float g_sims[NB * NB];

// ================= helpers =================
__device__ __forceinline__ uint32_t packbf(float v0, float v1, uint32_t& lo) {
    __nv_bfloat16 h0 = __float2bfloat16(v0);
    __nv_bfloat16 h1 = __float2bfloat16(v1);
    __nv_bfloat16 l0 = __float2bfloat16(v0 - __bfloat162float(h0));
    __nv_bfloat16 l1 = __float2bfloat16(v1 - __bfloat162float(h1));
    lo = (uint32_t)__bfloat16_as_ushort(l0) | ((uint32_t)__bfloat16_as_ushort(l1) << 16);
    return (uint32_t)__bfloat16_as_ushort(h0) | ((uint32_t)__bfloat16_as_ushort(h1) << 16);
}
__device__ __forceinline__ float bfhalf(uint32_t pk, int r) {
    uint16_t u = r ? (uint16_t)(pk >> 16) : (uint16_t)(pk & 0xffff);
    return __bfloat162float(__ushort_as_bfloat16(u));
}
__device__ __forceinline__ void mma16(float* c, uint32_t a0, uint32_t a1,
                                      uint32_t a2, uint32_t a3,
                                      uint32_t b0, uint32_t b1) {
    asm volatile(
        "mma.sync.aligned.m16n8k16.row.col.f32.bf16.bf16.f32 "
        "{%0,%1,%2,%3}, {%4,%5,%6,%7}, {%8,%9}, {%0,%1,%2,%3};"
        : "+f"(c[0]), "+f"(c[1]), "+f"(c[2]), "+f"(c[3])
        : "r"(a0), "r"(a1), "r"(a2), "r"(a3), "r"(b0), "r"(b1));
}
__device__ __forceinline__ uint32_t smem_u32(const void* p) {
    uint32_t a;
    asm("{ .reg .u64 t; cvta.to.shared.u64 t, %1; cvt.u32.u64 %0, t; }"
        : "=r"(a) : "l"(p));
    return a;
}
__device__ __forceinline__ void cpa16(uint32_t dst, const void* src) {
    asm volatile("cp.async.cg.shared.global [%0], [%1], 16;"
                 :: "r"(dst), "l"(src));
}
#define CPA_COMMIT() asm volatile("cp.async.commit_group;")
#define CPA_WAIT0()  asm volatile("cp.async.wait_group 0;")
#define CPA_WAIT1()  asm volatile("cp.async.wait_group 1;")

// ---- smem layout of fused kernel (bytes) ----
// S region: phase1 stages (2 x 51200); phase2 A-stages (2 x 33792)
#define ST_CTH 0
#define ST_CTL 16896
#define ST_WTH 33792
#define ST_WTL 42496
#define ST_SIZE 51200u
#define STA_SIZE 33792u
#define OFF_A2H 102400u
#define OFF_A2L 154624u
#define OFF_REDC 206848u
#define OFF_REDW 208896u
#define FUSED_SMEM 210944u

// phase-1 stage loader (ctx A tiles + word B tiles, hi/lo)
__device__ __forceinline__ void load_stage1(uint32_t dstbase,
    const uint32_t* aH, const uint32_t* aL,
    const uint32_t* bH, const uint32_t* bL,
    int k0, int s_base, int bsegs, int tid) {
    for (int i = tid; i < 2048; i += 256) {
        int h = i >> 10;
        int j = i & 1023;
        int kk = j >> 5, x4 = j & 31;
        const uint32_t* src = (h ? aL : aH) + (size_t)(k0 + kk) * SPAD + s_base + x4 * 4;
        cpa16(dstbase + (h ? ST_CTL : ST_CTH) + (uint32_t)(kk * 132 + x4 * 4) * 4, src);
    }
    int btot = 64 * bsegs;
    for (int i = tid; i < btot; i += 256) {
        int h = (i >= 32 * bsegs);
        int j = h ? i - 32 * bsegs : i;
        int kk = j / bsegs, x4 = j - kk * bsegs;
        const uint32_t* src = (h ? bL : bH) + (size_t)(k0 + kk) * NT + x4 * 4;
        cpa16(dstbase + (h ? ST_WTL : ST_WTH) + (uint32_t)(kk * 68 + x4 * 4) * 4, src);
    }
    CPA_COMMIT();
}
// phase-2 stage loader (G A tiles only, hi/lo)
__device__ __forceinline__ void load_stage2(uint32_t dstbase,
    const uint32_t* aH, const uint32_t* aL, int k0, int s_base, int tid) {
    for (int i = tid; i < 2048; i += 256) {
        int h = i >> 10;
        int j = i & 1023;
        int kk = j >> 5, x4 = j & 31;
        const uint32_t* src = (h ? aL : aH) + (size_t)(k0 + kk) * SPAD + s_base + x4 * 4;
        cpa16(dstbase + (h ? 16896u : 0u) + (uint32_t)(kk * 132 + x4 * 4) * 4, src);
    }
    CPA_COMMIT();
}

// ================= prep kernels =================
__global__ void pad_kernel(const float* __restrict__ lf) {
    size_t i = (size_t)blockIdx.x * blockDim.x + threadIdx.x;
    if (i < (size_t)NB * NC * SPAD) {
        int x = (int)(i % SPAD);
        size_t r = i / SPAD;
        g_ctxp[i] = (x < NS) ? lf[r * NS + x] : 0.f;
    }
}
// merged ctx + words packers
__global__ void prep_cw(const float* __restrict__ lf, const float* __restrict__ w) {
    size_t nctx = (size_t)NB * ND2 * SPAD;
    size_t nw = (size_t)NB * ND2 * NT;
    size_t i = (size_t)blockIdx.x * blockDim.x + threadIdx.x;
    if (i < nctx) {
        int s = (int)(i % SPAD);
        size_t r = i / SPAD;
        int d2 = (int)(r % ND2);
        int b = (int)(r / ND2);
        float v0 = 0.f, v1 = 0.f;
        if (s < NS) {
            v0 = lf[((size_t)b * NC + 2 * d2) * NS + s];
            v1 = lf[((size_t)b * NC + 2 * d2 + 1) * NS + s];
        }
        uint32_t lo;
        g_ctxPH[i] = packbf(v0, v1, lo);
        g_ctxPL[i] = lo;
    } else if (i < nctx + nw) {
        size_t j = i - nctx;
        int t = (int)(j % NT);
        size_t r = j / NT;
        int d2 = (int)(r % ND2);
        int c = (int)(r / ND2);
        float v0 = w[((size_t)c * NC + 2 * d2) * NT + t];
        float v1 = w[((size_t)c * NC + 2 * d2 + 1) * NT + t];
        uint32_t lo;
        g_wPH[j] = packbf(v0, v1, lo);
        g_wPL[j] = lo;
    }
}

// ================= gram (FFMA f32x2) -> packed GPH/GPL directly =============
__device__ __forceinline__ ull pack2s(float x) {
    ull r; asm("mov.b64 %0, {%1, %1};" : "=l"(r) : "f"(x)); return r;
}
__device__ __forceinline__ void ffma2(ull& d, ull a, ull b) {
    asm("fma.rn.f32x2 %0, %1, %2, %0;" : "+l"(d) : "l"(a), "l"(b));
}
__device__ __forceinline__ void unpack2(float& lo, float& hi, ull v) {
    asm("mov.b64 {%0, %1}, %2;" : "=f"(lo), "=f"(hi) : "l"(v));
}
__device__ __forceinline__ void fma8x8p(ull (&acc)[8][4],
                                        const float4 a0, const float4 a1,
                                        const ulonglong2 b01, const ulonglong2 b23) {
    float av[8] = {a0.x, a0.y, a0.z, a0.w, a1.x, a1.y, a1.z, a1.w};
    ull bp[4] = {b01.x, b01.y, b23.x, b23.y};
#pragma unroll
    for (int i = 0; i < 8; ++i) {
        ull ap = pack2s(av[i]);
        ffma2(acc[i][0], ap, bp[0]);
        ffma2(acc[i][1], ap, bp[1]);
        ffma2(acc[i][2], ap, bp[2]);
        ffma2(acc[i][3], ap, bp[3]);
    }
}

__global__ __launch_bounds__(256) void gram_kernel() {
    const int byA[6] = {0, 0, 0, 1, 1, 2};
    const int bxA[6] = {0, 1, 2, 1, 2, 2};
    int p = blockIdx.x, b = blockIdx.y;
    int i0 = byA[p] * 128, j0 = bxA[p] * 128;
    __shared__ float At[32 * 128];
    __shared__ float Bt[32 * 128];
    const float* cp = g_ctxp + (size_t)b * NC * SPAD;
    int tid = threadIdx.x;
    int ti = tid & 15, si = tid >> 4;
    int il = si * 8, jl = ti * 8;
    ull acc[8][4] = {};
    for (int kc = 0; kc < 24; ++kc) {
        int k0 = kc * 32;
        __syncthreads();
        for (int i4 = tid; i4 < 1024; i4 += 256) {
            int kk = i4 >> 5, x4 = i4 & 31;
            const float* base = cp + (size_t)(k0 + kk) * SPAD;
            ((float4*)At)[i4] = *(const float4*)(base + i0 + x4 * 4);
            ((float4*)Bt)[i4] = *(const float4*)(base + j0 + x4 * 4);
        }
        __syncthreads();
#pragma unroll 4
        for (int k = 0; k < 32; ++k) {
            float4 a0 = *(const float4*)&At[k * 128 + il];
            float4 a1 = *(const float4*)&At[k * 128 + il + 4];
            ulonglong2 b01 = *(const ulonglong2*)&Bt[k * 128 + jl];
            ulonglong2 b23 = *(const ulonglong2*)&Bt[k * 128 + jl + 4];
            fma8x8p(acc, a0, a1, b01, b23);
        }
    }
    float c[8][8];
#pragma unroll
    for (int ii = 0; ii < 8; ++ii)
#pragma unroll
        for (int j = 0; j < 4; ++j)
            unpack2(c[ii][2 * j], c[ii][2 * j + 1], acc[ii][j]);
    uint32_t* GbH = g_GPH + (size_t)b * NS2 * SPAD;
    uint32_t* GbL = g_GPL + (size_t)b * NS2 * SPAD;
    // packed rows (k-pairs along i)
#pragma unroll
    for (int m = 0; m < 4; ++m) {
        int k2 = (i0 + il) / 2 + m;
#pragma unroll
        for (int jj = 0; jj < 8; ++jj) {
            int s = j0 + jl + jj;
            uint32_t lo;
            uint32_t hi = packbf(c[2 * m][jj], c[2 * m + 1][jj], lo);
            GbH[(size_t)k2 * SPAD + s] = hi;
            GbL[(size_t)k2 * SPAD + s] = lo;
        }
    }
    if (i0 != j0) {  // symmetric block: packed rows along j
#pragma unroll
        for (int m = 0; m < 4; ++m) {
            int k2 = (j0 + jl) / 2 + m;
#pragma unroll
            for (int ii = 0; ii < 8; ++ii) {
                int s = i0 + il + ii;
                uint32_t lo;
                uint32_t hi = packbf(c[ii][2 * m], c[ii][2 * m + 1], lo);
                GbH[(size_t)k2 * SPAD + s] = hi;
                GbL[(size_t)k2 * SPAD + s] = lo;
            }
        }
    }
}

// ================= norms / gscore =================
__global__ void norms_kernel(const float* __restrict__ words,
                             const float* __restrict__ gfeat,
                             const float* __restrict__ sfeat) {
    int c = blockIdx.x;
    int tid = threadIdx.x;
    float s = 0.f;
    for (int d = 0; d < NC; ++d) {
        float v = words[((size_t)c * NC + d) * NT + tid];
        s = fmaf(v, v, s);
    }
    g_w1n[c * NT + tid] = sqrtf(s);
    float a = 0.f, bb = 0.f;
    for (int d = tid; d < NC; d += 64) {
        float v = gfeat[(size_t)c * NC + d];
        float w = sfeat[(size_t)c * NC + d];
        a = fmaf(v, v, a);
        bb = fmaf(w, w, bb);
    }
#pragma unroll
    for (int o = 16; o; o >>= 1) {
        a  += __shfl_xor_sync(0xffffffffu, a, o);
        bb += __shfl_xor_sync(0xffffffffu, bb, o);
    }
    __shared__ float r[4];
    int warp = tid >> 5, lane = tid & 31;
    if (lane == 0) { r[warp] = a; r[2 + warp] = bb; }
    __syncthreads();
    if (tid == 0) {
        g_gn[c] = sqrtf(r[0] + r[1]);
        g_sn[c] = sqrtf(r[2] + r[3]);
    }
}

__global__ void gscore_kernel(const float* __restrict__ gfeat,
                              const float* __restrict__ sfeat) {
    int i = blockIdx.x;
    int tid = threadIdx.x;
    int warp = tid >> 5, lane = tid & 31;
    for (int j = warp; j < NB; j += 8) {
        float acc = 0.f;
        for (int d = lane; d < NC; d += 32)
            acc = fmaf(gfeat[(size_t)i * NC + d], sfeat[(size_t)j * NC + d], acc);
#pragma unroll
        for (int o = 16; o; o >>= 1) acc += __shfl_xor_sync(0xffffffffu, acc, o);
        if (lane == 0) {
            float denom = fmaxf(g_gn[i] * g_sn[j], EPSV);
            g_sc0[i * NB + j] = TEMP3 * acc / denom;
        }
    }
}

// ================= fused pair kernel =================
__global__ __launch_bounds__(256, 1) void pair_fused(const int* __restrict__ caps) {
    extern __shared__ char smc[];
    uint32_t smb = smem_u32(smc);
    uint32_t* a2h = (uint32_t*)(smc + OFF_A2H);   // [192][68]
    uint32_t* a2l = (uint32_t*)(smc + OFF_A2L);
    float* redc = (float*)(smc + OFF_REDC);
    float* redw = (float*)(smc + OFF_REDW);

    int tid = threadIdx.x, wid = tid >> 5, lane = tid & 31;
    int g = lane >> 2, tg = lane & 3;
    int p = blockIdx.x, b = p % NB, c = p / NB;
    const uint32_t* cH = g_ctxPH + (size_t)b * ND2 * SPAD;
    const uint32_t* cL = g_ctxPL + (size_t)b * ND2 * SPAD;
    const uint32_t* wHp = g_wPH + (size_t)c * ND2 * NT;
    const uint32_t* wLp = g_wPL + (size_t)c * ND2 * NT;
    const uint32_t* GHp = g_GPH + (size_t)b * NS2 * SPAD;
    const uint32_t* GLp = g_GPL + (size_t)b * NS2 * SPAD;
    int cap = caps[c];
    int capN = (cap + 7) >> 3;
    int bsegs = 2 * capN;
    bool diag = (b == c);
    float* auD = g_a2uD + (size_t)b * SPAD * NT;

    float colacc[16] = {}, w12acc[16] = {};

    // ================= Phase 1: scores + softmax -> smem-packed a2u =========
    int pb = 0;
    load_stage1(smb, cH, cL, wHp, wLp, 0, 0, bsegs, tid);
    for (int st = 0; st < 3; ++st) {
        int s_base = st * 128;
        float acc[8][4] = {};
        for (int kc = 0; kc < 12; ++kc) {
            int gi = st * 12 + kc;
            if (gi < 35) {
                int nst = (kc < 11) ? st : st + 1;
                int nkc = (kc < 11) ? kc + 1 : 0;
                load_stage1(smb + (uint32_t)(pb ^ 1) * ST_SIZE,
                            cH, cL, wHp, wLp, nkc * 32, nst * 128, bsegs, tid);
                CPA_WAIT1();
            } else {
                CPA_WAIT0();
            }
            __syncthreads();
            uint32_t* base = (uint32_t*)(smc + (uint32_t)pb * ST_SIZE);
            uint32_t* cth = base;
            uint32_t* ctl = base + 4224;
            uint32_t* wth = base + 8448;
            uint32_t* wtl = base + 10624;
            int arow = wid * 16 + g;
#pragma unroll
            for (int j = 0; j < 4; ++j) {
                int jb = j * 8;
                int r0 = (jb + tg) * 132 + arow;
                int r1 = (jb + tg + 4) * 132 + arow;
                uint32_t ah0 = cth[r0], ah1 = cth[r0 + 8];
                uint32_t ah2 = cth[r1], ah3 = cth[r1 + 8];
                uint32_t al0 = ctl[r0], al1 = ctl[r0 + 8];
                uint32_t al2 = ctl[r1], al3 = ctl[r1 + 8];
#pragma unroll
                for (int nt = 0; nt < 8; ++nt) {
                    if (nt < capN) {
                        int b0i = (jb + tg) * 68 + nt * 8 + g;
                        int b1i = (jb + tg + 4) * 68 + nt * 8 + g;
                        uint32_t bh0 = wth[b0i], bh1 = wth[b1i];
                        uint32_t bl0 = wtl[b0i], bl1 = wtl[b1i];
                        mma16(acc[nt], ah0, ah1, ah2, ah3, bh0, bh1);
                        mma16(acc[nt], ah0, ah1, ah2, ah3, bl0, bl1);
                        mma16(acc[nt], al0, al1, al2, al3, bh0, bh1);
                    }
                }
            }
            __syncthreads();
            pb ^= 1;
        }
        // ---- fused masked softmax over t ----
        int s0 = s_base + wid * 16 + g;
        int s1 = s0 + 8;
        float mx0 = -1e30f, mx1 = -1e30f;
#pragma unroll
        for (int nt = 0; nt < 8; ++nt) {
            int col = nt * 8 + 2 * tg;
            if (col < cap)     { mx0 = fmaxf(mx0, acc[nt][0]); mx1 = fmaxf(mx1, acc[nt][2]); }
            if (col + 1 < cap) { mx0 = fmaxf(mx0, acc[nt][1]); mx1 = fmaxf(mx1, acc[nt][3]); }
        }
        mx0 = fmaxf(mx0, __shfl_xor_sync(0xffffffffu, mx0, 1));
        mx0 = fmaxf(mx0, __shfl_xor_sync(0xffffffffu, mx0, 2));
        mx1 = fmaxf(mx1, __shfl_xor_sync(0xffffffffu, mx1, 1));
        mx1 = fmaxf(mx1, __shfl_xor_sync(0xffffffffu, mx1, 2));
        float sm0 = 0.f, sm1 = 0.f;
#pragma unroll
        for (int nt = 0; nt < 8; ++nt) {
            int col = nt * 8 + 2 * tg;
            if (col < cap)     { sm0 += __expf(acc[nt][0] - mx0); sm1 += __expf(acc[nt][2] - mx1); }
            if (col + 1 < cap) { sm0 += __expf(acc[nt][1] - mx0); sm1 += __expf(acc[nt][3] - mx1); }
        }
        sm0 += __shfl_xor_sync(0xffffffffu, sm0, 1);
        sm0 += __shfl_xor_sync(0xffffffffu, sm0, 2);
        sm1 += __shfl_xor_sync(0xffffffffu, sm1, 1);
        sm1 += __shfl_xor_sync(0xffffffffu, sm1, 2);
        float inv0 = 1.f / sm0, inv1 = 1.f / sm1;
        bool v0ok = (s0 < NS), v1ok = (s1 < NS);
        bool eveng = ((g & 1) == 0);
#pragma unroll
        for (int nt = 0; nt < 8; ++nt) {
            int col = nt * 8 + 2 * tg;
            float e00 = (col < cap)     ? __expf(acc[nt][0] - mx0) : 0.f;
            float e01 = (col + 1 < cap) ? __expf(acc[nt][1] - mx0) : 0.f;
            float e10 = (col < cap)     ? __expf(acc[nt][2] - mx1) : 0.f;
            float e11 = (col + 1 < cap) ? __expf(acc[nt][3] - mx1) : 0.f;
            float u00 = __expf(TEMP1 * (e00 * inv0));
            float u01 = __expf(TEMP1 * (e01 * inv0));
            float u10 = __expf(TEMP1 * (e10 * inv1));
            float u11 = __expf(TEMP1 * (e11 * inv1));
            float a00 = v0ok ? u00 : 0.f, a01 = v0ok ? u01 : 0.f;
            float a10 = v1ok ? u10 : 0.f, a11 = v1ok ? u11 : 0.f;
            colacc[nt * 2 + 0] += a00 + a10;
            colacc[nt * 2 + 1] += a01 + a11;
            w12acc[nt * 2 + 0] += (v0ok ? u00 * acc[nt][0] : 0.f) + (v1ok ? u10 * acc[nt][2] : 0.f);
            w12acc[nt * 2 + 1] += (v0ok ? u01 * acc[nt][1] : 0.f) + (v1ok ? u11 * acc[nt][3] : 0.f);
            // partner (row s0+1 / s1+1) values via xor-4 lane exchange
            float q00 = __shfl_xor_sync(0xffffffffu, a00, 4);
            float q01 = __shfl_xor_sync(0xffffffffu, a01, 4);
            float q10 = __shfl_xor_sync(0xffffffffu, a10, 4);
            float q11 = __shfl_xor_sync(0xffffffffu, a11, 4);
            if (eveng) {
                uint32_t lo;
                int k2a = s0 >> 1, k2b = s1 >> 1;
                uint32_t hi = packbf(a00, q00, lo);
                a2h[k2a * 68 + col] = hi; a2l[k2a * 68 + col] = lo;
                hi = packbf(a01, q01, lo);
                a2h[k2a * 68 + col + 1] = hi; a2l[k2a * 68 + col + 1] = lo;
                hi = packbf(a10, q10, lo);
                a2h[k2b * 68 + col] = hi; a2l[k2b * 68 + col] = lo;
                hi = packbf(a11, q11, lo);
                a2h[k2b * 68 + col + 1] = hi; a2l[k2b * 68 + col + 1] = lo;
            }
            if (diag) {
                if (v0ok) *(float2*)&auD[(size_t)s0 * NT + col] = make_float2(a00, a01);
                if (v1ok) *(float2*)&auD[(size_t)s1 * NT + col] = make_float2(a10, a11);
            }
        }
    }
    // reduce colsum/w12
#pragma unroll
    for (int i = 0; i < 16; ++i) {
        float v = colacc[i], w = w12acc[i];
        v += __shfl_xor_sync(0xffffffffu, v, 4);
        v += __shfl_xor_sync(0xffffffffu, v, 8);
        v += __shfl_xor_sync(0xffffffffu, v, 16);
        w += __shfl_xor_sync(0xffffffffu, w, 4);
        w += __shfl_xor_sync(0xffffffffu, w, 8);
        w += __shfl_xor_sync(0xffffffffu, w, 16);
        colacc[i] = v; w12acc[i] = w;
    }
    __syncthreads();
    // phase-2 preload (S region free now)
    load_stage2(smb, GHp, GLp, 0, 0, tid);
    if (g == 0) {
#pragma unroll
        for (int i = 0; i < 16; ++i) {
            int col = (i >> 1) * 8 + 2 * tg + (i & 1);
            redc[wid * 64 + col] = colacc[i];
            redw[wid * 64 + col] = w12acc[i];
        }
    }
    __syncthreads();
    if (tid < 64) {
        float cs = 0.f, ws = 0.f;
#pragma unroll
        for (int w = 0; w < 8; ++w) { cs += redc[w * 64 + tid]; ws += redw[w * 64 + tid]; }
        g_cols[p * 64 + tid] = cs;
        g_w12[p * 64 + tid] = ws;
    }
    __syncthreads();

    // ================= Phase 2: Y = G @ a2u (B from smem), contraction =======
    float w2acc[16] = {};
    pb = 0;
    for (int st = 0; st < 3; ++st) {
        int s_base = st * 128;
        float acc[8][4] = {};
        for (int kc = 0; kc < 6; ++kc) {
            int gi = st * 6 + kc;
            if (gi < 17) {
                int nst = (kc < 5) ? st : st + 1;
                int nkc = (kc < 5) ? kc + 1 : 0;
                load_stage2(smb + (uint32_t)(pb ^ 1) * STA_SIZE,
                            GHp, GLp, nkc * 32, nst * 128, tid);
                CPA_WAIT1();
            } else {
                CPA_WAIT0();
            }
            __syncthreads();
            uint32_t* base = (uint32_t*)(smc + (uint32_t)pb * STA_SIZE);
            uint32_t* cth = base;
            uint32_t* ctl = base + 4224;
            int arow = wid * 16 + g;
            int kbase = kc * 32;
#pragma unroll
            for (int j = 0; j < 4; ++j) {
                int jb = j * 8;
                int r0 = (jb + tg) * 132 + arow;
                int r1 = (jb + tg + 4) * 132 + arow;
                uint32_t ah0 = cth[r0], ah1 = cth[r0 + 8];
                uint32_t ah2 = cth[r1], ah3 = cth[r1 + 8];
                uint32_t al0 = ctl[r0], al1 = ctl[r0 + 8];
                uint32_t al2 = ctl[r1], al3 = ctl[r1 + 8];
                int bb0 = (kbase + jb + tg) * 68;
                int bb1 = (kbase + jb + tg + 4) * 68;
#pragma unroll
                for (int nt = 0; nt < 8; ++nt) {
                    if (nt < capN) {
                        int b0i = bb0 + nt * 8 + g;
                        int b1i = bb1 + nt * 8 + g;
                        uint32_t bh0 = a2h[b0i], bh1 = a2h[b1i];
                        uint32_t bl0 = a2l[b0i], bl1 = a2l[b1i];
                        mma16(acc[nt], ah0, ah1, ah2, ah3, bh0, bh1);
                        mma16(acc[nt], ah0, ah1, ah2, ah3, bl0, bl1);
                        mma16(acc[nt], al0, al1, al2, al3, bh0, bh1);
                    }
                }
            }
            __syncthreads();
            pb ^= 1;
        }
        // contraction: w2[t] += a2u[s,t] * Y[s,t], a2u = hi+lo from smem
        int s0 = s_base + wid * 16 + g;
        int s1 = s0 + 8;
        int k20 = s0 >> 1, r0p = s0 & 1;
        int k21 = s1 >> 1, r1p = s1 & 1;
#pragma unroll
        for (int nt = 0; nt < 8; ++nt) {
            int col = nt * 8 + 2 * tg;
            float a00 = bfhalf(a2h[k20 * 68 + col], r0p) + bfhalf(a2l[k20 * 68 + col], r0p);
            float a01 = bfhalf(a2h[k20 * 68 + col + 1], r0p) + bfhalf(a2l[k20 * 68 + col + 1], r0p);
            float a10 = bfhalf(a2h[k21 * 68 + col], r1p) + bfhalf(a2l[k21 * 68 + col], r1p);
            float a11 = bfhalf(a2h[k21 * 68 + col + 1], r1p) + bfhalf(a2l[k21 * 68 + col + 1], r1p);
            w2acc[nt * 2 + 0] += a00 * acc[nt][0] + a10 * acc[nt][2];
            w2acc[nt * 2 + 1] += a01 * acc[nt][1] + a11 * acc[nt][3];
        }
    }
#pragma unroll
    for (int i = 0; i < 16; ++i) {
        float v = w2acc[i];
        v += __shfl_xor_sync(0xffffffffu, v, 4);
        v += __shfl_xor_sync(0xffffffffu, v, 8);
        v += __shfl_xor_sync(0xffffffffu, v, 16);
        w2acc[i] = v;
    }
    __syncthreads();
    if (g == 0) {
#pragma unroll
        for (int i = 0; i < 16; ++i) {
            int col = (i >> 1) * 8 + 2 * tg + (i & 1);
            redc[wid * 64 + col] = w2acc[i];
        }
    }
    __syncthreads();
    if (tid < 64) {
        float s = 0.f;
#pragma unroll
        for (int w = 0; w < 8; ++w) s += redc[w * 64 + tid];
        g_w2[p * 64 + tid] = s;
    }
}

// ================= finalizers =================
__global__ void csim_kernel(const int* __restrict__ caps) {
    int p = blockIdx.x, b = p % NB, c = p / NB;
    int t = threadIdx.x;
    float cs = g_cols[p * 64 + t];
    float ci = 1.f / cs;
    float w12 = g_w12[p * 64 + t] * ci;
    float w2 = ci * sqrtf(fmaxf(g_w2[p * 64 + t], 0.f));
    float w1 = g_w1n[c * 64 + t];
    float sim = w12 / fmaxf(w1 * w2, EPSV);
    float row = (t < caps[c]) ? __expf(TEMP2 * sim) : 0.f;
#pragma unroll
    for (int o = 16; o; o >>= 1) row += __shfl_xor_sync(0xffffffffu, row, o);
    __shared__ float sred[2];
    if ((t & 31) == 0) sred[t >> 5] = row;
    __syncthreads();
    if (t == 0) g_sims[b * NB + c] = TEMP3 * logf(sred[0] + sred[1]);
}

__global__ void att_kernel(float* __restrict__ ao) {
    int b = blockIdx.x;
    int p = b * NB + b;
    int tid = threadIdx.x;
    __shared__ float ci[64];
    if (tid < 64) ci[tid] = 1.f / g_cols[p * 64 + tid];
    __syncthreads();
    const float* au = g_a2uD + (size_t)b * SPAD * NT;
    for (int i = tid; i < NS * NT; i += 256) {
        int s = i >> 6, t = i & 63;
        ao[((size_t)b * NT + t) * NS + s] = au[(size_t)s * NT + t] * ci[t];
    }
}

__global__ void loss_kernel(float* __restrict__ out) {
    __shared__ float part[4][NB];
    int i = threadIdx.x;
    if (i < NB) {
        const float* Ms = g_sims;
        const float* Mg = g_sc0;
        float m, sum;
        m = -INFINITY;
        for (int j = 0; j < NB; ++j) m = fmaxf(m, Ms[i * NB + j]);
        sum = 0.f;
        for (int j = 0; j < NB; ++j) sum += expf(Ms[i * NB + j] - m);
        part[0][i] = m + logf(sum) - Ms[i * NB + i];
        m = -INFINITY;
        for (int j = 0; j < NB; ++j) m = fmaxf(m, Ms[j * NB + i]);
        sum = 0.f;
        for (int j = 0; j < NB; ++j) sum += expf(Ms[j * NB + i] - m);
        part[1][i] = m + logf(sum) - Ms[i * NB + i];
        m = -INFINITY;
        for (int j = 0; j < NB; ++j) m = fmaxf(m, Mg[i * NB + j]);
        sum = 0.f;
        for (int j = 0; j < NB; ++j) sum += expf(Mg[i * NB + j] - m);
        part[2][i] = m + logf(sum) - Mg[i * NB + i];
        m = -INFINITY;
        for (int j = 0; j < NB; ++j) m = fmaxf(m, Mg[j * NB + i]);
        sum = 0.f;
        for (int j = 0; j < NB; ++j) sum += expf(Mg[j * NB + i] - m);
        part[3][i] = m + logf(sum) - Mg[i * NB + i];
    }
    __syncthreads();
    if (i == 0) {
        float l = 0.f;
        for (int k = 0; k < 4; ++k) {
            float s = 0.f;
            for (int j = 0; j < NB; ++j) s += part[k][j];
            l += s * (1.f / (float)NB);
        }
        out[0] = l;
    }
}

// ================= launch =================
extern "C" void kernel_launch(void* const* d_in, const int* in_sizes, int n_in,
                              void* d_out, int out_size) {
    const float* gfeat  = (const float*)d_in[0];
    const float* localf = (const float*)d_in[1];
    const float* words  = (const float*)d_in[2];
    const float* sfeat  = (const float*)d_in[3];
    const int*   caps   = (const int*)d_in[4];
    float* out = (float*)d_out;

    cudaFuncSetAttribute(pair_fused, cudaFuncAttributeMaxDynamicSharedMemorySize, FUSED_SMEM);

    size_t n_pad = (size_t)NB * NC * SPAD;
    size_t n_cw = (size_t)NB * ND2 * SPAD + (size_t)NB * ND2 * NT;
    pad_kernel<<<(unsigned)((n_pad + 255) / 256), 256>>>(localf);      // launch 1
    gram_kernel<<<dim3(6, NB), 256>>>();                               // launch 2
    prep_cw<<<(unsigned)((n_cw + 255) / 256), 256>>>(localf, words);   // launch 3
    pair_fused<<<NPAIR, 256, FUSED_SMEM>>>(caps);                      // launch 4 (ncu)

    norms_kernel<<<NB, 64>>>(words, gfeat, sfeat);
    gscore_kernel<<<NB, 256>>>(gfeat, sfeat);
    csim_kernel<<<NPAIR, 64>>>(caps);

    int wa = (out_size >= 1 + NB * NT * NS) ? 1 : 0;
    if (wa) att_kernel<<<NB, 256>>>(out + 1);
    loss_kernel<<<1, 64>>>(out);
}

// round 16
// speedup vs baseline: 1.2476x; 1.2476x over previous
#include <cuda_runtime.h>
#include <cuda_bf16.h>
#include <math.h>
#include <stdint.h>

#define NB 48
#define NC 768
#define NS 361
#define NT 64
#define SPAD 384
#define ND2 (NC / 2)
#define NS2 (SPAD / 2)
#define NPAIR (NB * NB)

#define TEMP1 4.0f
#define TEMP2 5.0f
#define TEMP3 10.0f
#define EPSV  1e-8f

typedef unsigned long long ull;

// ================= device scratch =================
__device__ float g_ctxp[(size_t)NB * NC * SPAD];      // padded ctx (gram input)
__device__ uint32_t g_ctxPH[(size_t)NB * ND2 * SPAD]; // bf16x2 hi ctx [b][d2][s]
__device__ uint32_t g_ctxPL[(size_t)NB * ND2 * SPAD];
__device__ uint32_t g_wPH[(size_t)NB * ND2 * NT];     // bf16x2 hi words [c][d2][t]
__device__ uint32_t g_wPL[(size_t)NB * ND2 * NT];
__device__ uint32_t g_GPH[(size_t)NB * NS2 * SPAD];   // bf16x2 hi G [b][k2][s]
__device__ uint32_t g_GPL[(size_t)NB * NS2 * SPAD];
__device__ uint32_t g_aPH[(size_t)NPAIR * NS2 * NT];  // bf16x2 hi a2u [p][s2][t]
__device__ uint32_t g_aPL[(size_t)NPAIR * NS2 * NT];
__device__ float g_a2uD[(size_t)NB * SPAD * NT];      // fp32 a2u, diagonal pairs only
__device__ float g_cols[NPAIR * NT];
__device__ float g_w12[NPAIR * NT];
__device__ float g_w2[NPAIR * NT];
__device__ float g_w1n[NB * NT];
__device__ float g_gn[NB];
__device__ float g_sn[NB];
__device__ float g_sc0[NB * NB];
__device__ float g_sims[NB * NB];

// ================= helpers =================
__device__ __forceinline__ uint32_t packbf(float v0, float v1, uint32_t& lo) {
    __nv_bfloat16 h0 = __float2bfloat16(v0);
    __nv_bfloat16 h1 = __float2bfloat16(v1);
    __nv_bfloat16 l0 = __float2bfloat16(v0 - __bfloat162float(h0));
    __nv_bfloat16 l1 = __float2bfloat16(v1 - __bfloat162float(h1));
    lo = (uint32_t)__bfloat16_as_ushort(l0) | ((uint32_t)__bfloat16_as_ushort(l1) << 16);
    return (uint32_t)__bfloat16_as_ushort(h0) | ((uint32_t)__bfloat16_as_ushort(h1) << 16);
}
__device__ __forceinline__ float bfhalf(uint32_t pk, int r) {
    uint16_t u = r ? (uint16_t)(pk >> 16) : (uint16_t)(pk & 0xffff);
    return __bfloat162float(__ushort_as_bfloat16(u));
}
__device__ __forceinline__ void mma16(float* c, uint32_t a0, uint32_t a1,
                                      uint32_t a2, uint32_t a3,
                                      uint32_t b0, uint32_t b1) {
    asm volatile(
        "mma.sync.aligned.m16n8k16.row.col.f32.bf16.bf16.f32 "
        "{%0,%1,%2,%3}, {%4,%5,%6,%7}, {%8,%9}, {%0,%1,%2,%3};"
        : "+f"(c[0]), "+f"(c[1]), "+f"(c[2]), "+f"(c[3])
        : "r"(a0), "r"(a1), "r"(a2), "r"(a3), "r"(b0), "r"(b1));
}
__device__ __forceinline__ uint32_t smem_u32(const void* p) {
    uint32_t a;
    asm("{ .reg .u64 t; cvta.to.shared.u64 t, %1; cvt.u32.u64 %0, t; }"
        : "=r"(a) : "l"(p));
    return a;
}
__device__ __forceinline__ void cpa16(uint32_t dst, const void* src) {
    asm volatile("cp.async.cg.shared.global [%0], [%1], 16;"
                 :: "r"(dst), "l"(src));
}
#define CPA_COMMIT() asm volatile("cp.async.commit_group;")
#define CPA_WAIT0()  asm volatile("cp.async.wait_group 0;")
#define CPA_WAIT1()  asm volatile("cp.async.wait_group 1;")

// stage layout (bytes within one 51200-B stage)
#define ST_CTH 0
#define ST_CTL 16896
#define ST_WTH 33792
#define ST_WTL 42496
#define ST_SIZE 51200u

__device__ __forceinline__ void load_stage(uint32_t dstbase,
    const uint32_t* aH, const uint32_t* aL,
    const uint32_t* bH, const uint32_t* bL,
    int k0, int s_base, int bsegs, int tid) {
    for (int i = tid; i < 2048; i += 256) {
        int h = i >> 10;
        int j = i & 1023;
        int kk = j >> 5, x4 = j & 31;
        const uint32_t* src = (h ? aL : aH) + (size_t)(k0 + kk) * SPAD + s_base + x4 * 4;
        cpa16(dstbase + (h ? ST_CTL : ST_CTH) + (uint32_t)(kk * 132 + x4 * 4) * 4, src);
    }
    int btot = 64 * bsegs;
    for (int i = tid; i < btot; i += 256) {
        int h = (i >= 32 * bsegs);
        int j = h ? i - 32 * bsegs : i;
        int kk = j / bsegs, x4 = j - kk * bsegs;
        const uint32_t* src = (h ? bL : bH) + (size_t)(k0 + kk) * NT + x4 * 4;
        cpa16(dstbase + (h ? ST_WTL : ST_WTH) + (uint32_t)(kk * 68 + x4 * 4) * 4, src);
    }
    CPA_COMMIT();
}

// ================= prep kernels =================
__global__ void pad_kernel(const float* __restrict__ lf) {
    size_t i = (size_t)blockIdx.x * blockDim.x + threadIdx.x;
    if (i < (size_t)NB * NC * SPAD) {
        int x = (int)(i % SPAD);
        size_t r = i / SPAD;
        g_ctxp[i] = (x < NS) ? lf[r * NS + x] : 0.f;
    }
}
__global__ void prep_cw(const float* __restrict__ lf, const float* __restrict__ w) {
    size_t nctx = (size_t)NB * ND2 * SPAD;
    size_t nw = (size_t)NB * ND2 * NT;
    size_t i = (size_t)blockIdx.x * blockDim.x + threadIdx.x;
    if (i < nctx) {
        int s = (int)(i % SPAD);
        size_t r = i / SPAD;
        int d2 = (int)(r % ND2);
        int b = (int)(r / ND2);
        float v0 = 0.f, v1 = 0.f;
        if (s < NS) {
            v0 = lf[((size_t)b * NC + 2 * d2) * NS + s];
            v1 = lf[((size_t)b * NC + 2 * d2 + 1) * NS + s];
        }
        uint32_t lo;
        g_ctxPH[i] = packbf(v0, v1, lo);
        g_ctxPL[i] = lo;
    } else if (i < nctx + nw) {
        size_t j = i - nctx;
        int t = (int)(j % NT);
        size_t r = j / NT;
        int d2 = (int)(r % ND2);
        int c = (int)(r / ND2);
        float v0 = w[((size_t)c * NC + 2 * d2) * NT + t];
        float v1 = w[((size_t)c * NC + 2 * d2 + 1) * NT + t];
        uint32_t lo;
        g_wPH[j] = packbf(v0, v1, lo);
        g_wPL[j] = lo;
    }
}

// ================= gram (FFMA f32x2) -> packed GPH/GPL directly =============
__device__ __forceinline__ ull pack2s(float x) {
    ull r; asm("mov.b64 %0, {%1, %1};" : "=l"(r) : "f"(x)); return r;
}
__device__ __forceinline__ void ffma2(ull& d, ull a, ull b) {
    asm("fma.rn.f32x2 %0, %1, %2, %0;" : "+l"(d) : "l"(a), "l"(b));
}
__device__ __forceinline__ void unpack2(float& lo, float& hi, ull v) {
    asm("mov.b64 {%0, %1}, %2;" : "=f"(lo), "=f"(hi) : "l"(v));
}
__device__ __forceinline__ void fma8x8p(ull (&acc)[8][4],
                                        const float4 a0, const float4 a1,
                                        const ulonglong2 b01, const ulonglong2 b23) {
    float av[8] = {a0.x, a0.y, a0.z, a0.w, a1.x, a1.y, a1.z, a1.w};
    ull bp[4] = {b01.x, b01.y, b23.x, b23.y};
#pragma unroll
    for (int i = 0; i < 8; ++i) {
        ull ap = pack2s(av[i]);
        ffma2(acc[i][0], ap, bp[0]);
        ffma2(acc[i][1], ap, bp[1]);
        ffma2(acc[i][2], ap, bp[2]);
        ffma2(acc[i][3], ap, bp[3]);
    }
}

__global__ __launch_bounds__(256) void gram_kernel() {
    const int byA[6] = {0, 0, 0, 1, 1, 2};
    const int bxA[6] = {0, 1, 2, 1, 2, 2};
    int p = blockIdx.x, b = blockIdx.y;
    int i0 = byA[p] * 128, j0 = bxA[p] * 128;
    __shared__ float At[32 * 128];
    __shared__ float Bt[32 * 128];
    const float* cp = g_ctxp + (size_t)b * NC * SPAD;
    int tid = threadIdx.x;
    int ti = tid & 15, si = tid >> 4;
    int il = si * 8, jl = ti * 8;
    ull acc[8][4] = {};
    for (int kc = 0; kc < 24; ++kc) {
        int k0 = kc * 32;
        __syncthreads();
        for (int i4 = tid; i4 < 1024; i4 += 256) {
            int kk = i4 >> 5, x4 = i4 & 31;
            const float* base = cp + (size_t)(k0 + kk) * SPAD;
            ((float4*)At)[i4] = *(const float4*)(base + i0 + x4 * 4);
            ((float4*)Bt)[i4] = *(const float4*)(base + j0 + x4 * 4);
        }
        __syncthreads();
#pragma unroll 4
        for (int k = 0; k < 32; ++k) {
            float4 a0 = *(const float4*)&At[k * 128 + il];
            float4 a1 = *(const float4*)&At[k * 128 + il + 4];
            ulonglong2 b01 = *(const ulonglong2*)&Bt[k * 128 + jl];
            ulonglong2 b23 = *(const ulonglong2*)&Bt[k * 128 + jl + 4];
            fma8x8p(acc, a0, a1, b01, b23);
        }
    }
    float c[8][8];
#pragma unroll
    for (int ii = 0; ii < 8; ++ii)
#pragma unroll
        for (int j = 0; j < 4; ++j)
            unpack2(c[ii][2 * j], c[ii][2 * j + 1], acc[ii][j]);
    uint32_t* GbH = g_GPH + (size_t)b * NS2 * SPAD;
    uint32_t* GbL = g_GPL + (size_t)b * NS2 * SPAD;
#pragma unroll
    for (int m = 0; m < 4; ++m) {
        int k2 = (i0 + il) / 2 + m;
#pragma unroll
        for (int jj = 0; jj < 8; ++jj) {
            int s = j0 + jl + jj;
            uint32_t lo;
            uint32_t hi = packbf(c[2 * m][jj], c[2 * m + 1][jj], lo);
            GbH[(size_t)k2 * SPAD + s] = hi;
            GbL[(size_t)k2 * SPAD + s] = lo;
        }
    }
    if (i0 != j0) {
#pragma unroll
        for (int m = 0; m < 4; ++m) {
            int k2 = (j0 + jl) / 2 + m;
#pragma unroll
            for (int ii = 0; ii < 8; ++ii) {
                int s = i0 + il + ii;
                uint32_t lo;
                uint32_t hi = packbf(c[ii][2 * m], c[ii][2 * m + 1], lo);
                GbH[(size_t)k2 * SPAD + s] = hi;
                GbL[(size_t)k2 * SPAD + s] = lo;
            }
        }
    }
}

// ================= norms / gscore =================
__global__ void norms_kernel(const float* __restrict__ words,
                             const float* __restrict__ gfeat,
                             const float* __restrict__ sfeat) {
    int c = blockIdx.x;
    int tid = threadIdx.x;
    float s = 0.f;
    for (int d = 0; d < NC; ++d) {
        float v = words[((size_t)c * NC + d) * NT + tid];
        s = fmaf(v, v, s);
    }
    g_w1n[c * NT + tid] = sqrtf(s);
    float a = 0.f, bb = 0.f;
    for (int d = tid; d < NC; d += 64) {
        float v = gfeat[(size_t)c * NC + d];
        float w = sfeat[(size_t)c * NC + d];
        a = fmaf(v, v, a);
        bb = fmaf(w, w, bb);
    }
#pragma unroll
    for (int o = 16; o; o >>= 1) {
        a  += __shfl_xor_sync(0xffffffffu, a, o);
        bb += __shfl_xor_sync(0xffffffffu, bb, o);
    }
    __shared__ float r[4];
    int warp = tid >> 5, lane = tid & 31;
    if (lane == 0) { r[warp] = a; r[2 + warp] = bb; }
    __syncthreads();
    if (tid == 0) {
        g_gn[c] = sqrtf(r[0] + r[1]);
        g_sn[c] = sqrtf(r[2] + r[3]);
    }
}

__global__ void gscore_kernel(const float* __restrict__ gfeat,
                              const float* __restrict__ sfeat) {
    int i = blockIdx.x;
    int tid = threadIdx.x;
    int warp = tid >> 5, lane = tid & 31;
    for (int j = warp; j < NB; j += 8) {
        float acc = 0.f;
        for (int d = lane; d < NC; d += 32)
            acc = fmaf(gfeat[(size_t)i * NC + d], sfeat[(size_t)j * NC + d], acc);
#pragma unroll
        for (int o = 16; o; o >>= 1) acc += __shfl_xor_sync(0xffffffffu, acc, o);
        if (lane == 0) {
            float denom = fmaxf(g_gn[i] * g_sn[j], EPSV);
            g_sc0[i * NB + j] = TEMP3 * acc / denom;
        }
    }
}

// ================= Kernel A: bf16 mma, double-buffered, packed a2u out ======
#define A_REDC 102400
#define A_REDW 104448
#define A_SMEM 106496

__global__ __launch_bounds__(256, 2) void scoreA_kernel(const int* __restrict__ caps) {
    extern __shared__ char smc[];
    uint32_t smb = smem_u32(smc);
    float* redc = (float*)(smc + A_REDC);
    float* redw = (float*)(smc + A_REDW);

    int tid = threadIdx.x, wid = tid >> 5, lane = tid & 31;
    int g = lane >> 2, tg = lane & 3;
    int p = blockIdx.x, b = p % NB, c = p / NB;
    const uint32_t* cH = g_ctxPH + (size_t)b * ND2 * SPAD;
    const uint32_t* cL = g_ctxPL + (size_t)b * ND2 * SPAD;
    const uint32_t* wHp = g_wPH + (size_t)c * ND2 * NT;
    const uint32_t* wLp = g_wPL + (size_t)c * ND2 * NT;
    int cap = caps[c];
    int capN = (cap + 7) >> 3;
    int bsegs = 2 * capN;
    bool diag = (b == c);
    float* auD = g_a2uD + (size_t)b * SPAD * NT;
    uint32_t* aPH = g_aPH + (size_t)p * NS2 * NT;
    uint32_t* aPL = g_aPL + (size_t)p * NS2 * NT;

    float colacc[16] = {}, w12acc[16] = {};

    int pb = 0;
    load_stage(smb, cH, cL, wHp, wLp, 0, 0, bsegs, tid);

    for (int st = 0; st < 3; ++st) {
        int s_base = st * 128;
        float acc[8][4] = {};
        for (int kc = 0; kc < 12; ++kc) {
            int gi = st * 12 + kc;
            if (gi < 35) {
                int nst = (kc < 11) ? st : st + 1;
                int nkc = (kc < 11) ? kc + 1 : 0;
                load_stage(smb + (uint32_t)(pb ^ 1) * ST_SIZE,
                           cH, cL, wHp, wLp, nkc * 32, nst * 128, bsegs, tid);
                CPA_WAIT1();
            } else {
                CPA_WAIT0();
            }
            __syncthreads();
            uint32_t* base = (uint32_t*)(smc + (uint32_t)pb * ST_SIZE);
            uint32_t* cth = base;
            uint32_t* ctl = base + 4224;
            uint32_t* wth = base + 8448;
            uint32_t* wtl = base + 10624;
            int arow = wid * 16 + g;
#pragma unroll
            for (int j = 0; j < 4; ++j) {
                int jb = j * 8;
                int r0 = (jb + tg) * 132 + arow;
                int r1 = (jb + tg + 4) * 132 + arow;
                uint32_t ah0 = cth[r0], ah1 = cth[r0 + 8];
                uint32_t ah2 = cth[r1], ah3 = cth[r1 + 8];
                uint32_t al0 = ctl[r0], al1 = ctl[r0 + 8];
                uint32_t al2 = ctl[r1], al3 = ctl[r1 + 8];
#pragma unroll
                for (int nt = 0; nt < 8; ++nt) {
                    if (nt < capN) {
                        int b0i = (jb + tg) * 68 + nt * 8 + g;
                        int b1i = (jb + tg + 4) * 68 + nt * 8 + g;
                        uint32_t bh0 = wth[b0i], bh1 = wth[b1i];
                        uint32_t bl0 = wtl[b0i], bl1 = wtl[b1i];
                        mma16(acc[nt], ah0, ah1, ah2, ah3, bh0, bh1);
                        mma16(acc[nt], ah0, ah1, ah2, ah3, bl0, bl1);
                        mma16(acc[nt], al0, al1, al2, al3, bh0, bh1);
                    }
                }
            }
            __syncthreads();
            pb ^= 1;
        }
        // ---- fused masked softmax over t ----
        int s0 = s_base + wid * 16 + g;
        int s1 = s0 + 8;
        float mx0 = -1e30f, mx1 = -1e30f;
#pragma unroll
        for (int nt = 0; nt < 8; ++nt) {
            int col = nt * 8 + 2 * tg;
            if (col < cap)     { mx0 = fmaxf(mx0, acc[nt][0]); mx1 = fmaxf(mx1, acc[nt][2]); }
            if (col + 1 < cap) { mx0 = fmaxf(mx0, acc[nt][1]); mx1 = fmaxf(mx1, acc[nt][3]); }
        }
        mx0 = fmaxf(mx0, __shfl_xor_sync(0xffffffffu, mx0, 1));
        mx0 = fmaxf(mx0, __shfl_xor_sync(0xffffffffu, mx0, 2));
        mx1 = fmaxf(mx1, __shfl_xor_sync(0xffffffffu, mx1, 1));
        mx1 = fmaxf(mx1, __shfl_xor_sync(0xffffffffu, mx1, 2));
        float sm0 = 0.f, sm1 = 0.f;
#pragma unroll
        for (int nt = 0; nt < 8; ++nt) {
            int col = nt * 8 + 2 * tg;
            if (col < cap)     { sm0 += __expf(acc[nt][0] - mx0); sm1 += __expf(acc[nt][2] - mx1); }
            if (col + 1 < cap) { sm0 += __expf(acc[nt][1] - mx0); sm1 += __expf(acc[nt][3] - mx1); }
        }
        sm0 += __shfl_xor_sync(0xffffffffu, sm0, 1);
        sm0 += __shfl_xor_sync(0xffffffffu, sm0, 2);
        sm1 += __shfl_xor_sync(0xffffffffu, sm1, 1);
        sm1 += __shfl_xor_sync(0xffffffffu, sm1, 2);
        float inv0 = 1.f / sm0, inv1 = 1.f / sm1;
        bool v0ok = (s0 < NS), v1ok = (s1 < NS);
        bool eveng = ((g & 1) == 0);
#pragma unroll
        for (int nt = 0; nt < 8; ++nt) {
            int col = nt * 8 + 2 * tg;
            float e00 = (col < cap)     ? __expf(acc[nt][0] - mx0) : 0.f;
            float e01 = (col + 1 < cap) ? __expf(acc[nt][1] - mx0) : 0.f;
            float e10 = (col < cap)     ? __expf(acc[nt][2] - mx1) : 0.f;
            float e11 = (col + 1 < cap) ? __expf(acc[nt][3] - mx1) : 0.f;
            float u00 = __expf(TEMP1 * (e00 * inv0));
            float u01 = __expf(TEMP1 * (e01 * inv0));
            float u10 = __expf(TEMP1 * (e10 * inv1));
            float u11 = __expf(TEMP1 * (e11 * inv1));
            float a00 = v0ok ? u00 : 0.f, a01 = v0ok ? u01 : 0.f;
            float a10 = v1ok ? u10 : 0.f, a11 = v1ok ? u11 : 0.f;
            colacc[nt * 2 + 0] += a00 + a10;
            colacc[nt * 2 + 1] += a01 + a11;
            w12acc[nt * 2 + 0] += (v0ok ? u00 * acc[nt][0] : 0.f) + (v1ok ? u10 * acc[nt][2] : 0.f);
            w12acc[nt * 2 + 1] += (v0ok ? u01 * acc[nt][1] : 0.f) + (v1ok ? u11 * acc[nt][3] : 0.f);
            // partner row (s +/- 1) values via xor-4 lane exchange
            float q00 = __shfl_xor_sync(0xffffffffu, a00, 4);
            float q01 = __shfl_xor_sync(0xffffffffu, a01, 4);
            float q10 = __shfl_xor_sync(0xffffffffu, a10, 4);
            float q11 = __shfl_xor_sync(0xffffffffu, a11, 4);
            if (eveng) {
                int k2a = s0 >> 1, k2b = s1 >> 1;
                uint32_t lo;
                uint32_t hi = packbf(a00, q00, lo);
                aPH[(size_t)k2a * NT + col] = hi; aPL[(size_t)k2a * NT + col] = lo;
                hi = packbf(a01, q01, lo);
                aPH[(size_t)k2a * NT + col + 1] = hi; aPL[(size_t)k2a * NT + col + 1] = lo;
                hi = packbf(a10, q10, lo);
                aPH[(size_t)k2b * NT + col] = hi; aPL[(size_t)k2b * NT + col] = lo;
                hi = packbf(a11, q11, lo);
                aPH[(size_t)k2b * NT + col + 1] = hi; aPL[(size_t)k2b * NT + col + 1] = lo;
            }
            if (diag) {
                if (v0ok) *(float2*)&auD[(size_t)s0 * NT + col] = make_float2(a00, a01);
                if (v1ok) *(float2*)&auD[(size_t)s1 * NT + col] = make_float2(a10, a11);
            }
        }
    }
#pragma unroll
    for (int i = 0; i < 16; ++i) {
        float v = colacc[i], w = w12acc[i];
        v += __shfl_xor_sync(0xffffffffu, v, 4);
        v += __shfl_xor_sync(0xffffffffu, v, 8);
        v += __shfl_xor_sync(0xffffffffu, v, 16);
        w += __shfl_xor_sync(0xffffffffu, w, 4);
        w += __shfl_xor_sync(0xffffffffu, w, 8);
        w += __shfl_xor_sync(0xffffffffu, w, 16);
        colacc[i] = v; w12acc[i] = w;
    }
    __syncthreads();
    if (g == 0) {
#pragma unroll
        for (int i = 0; i < 16; ++i) {
            int col = (i >> 1) * 8 + 2 * tg + (i & 1);
            redc[wid * 64 + col] = colacc[i];
            redw[wid * 64 + col] = w12acc[i];
        }
    }
    __syncthreads();
    if (tid < 64) {
        float cs = 0.f, ws = 0.f;
#pragma unroll
        for (int w = 0; w < 8; ++w) { cs += redc[w * 64 + tid]; ws += redw[w * 64 + tid]; }
        g_cols[p * 64 + tid] = cs;
        g_w12[p * 64 + tid] = ws;
    }
}

// ================= Kernel B: bf16 mma Gram quadratic form, double-buffered ==
#define B_W2R 102400
#define B_SMEM 104448

__global__ __launch_bounds__(256, 2) void w2B_kernel(const int* __restrict__ caps) {
    extern __shared__ char smc[];
    uint32_t smb = smem_u32(smc);
    float* w2red = (float*)(smc + B_W2R);

    int tid = threadIdx.x, wid = tid >> 5, lane = tid & 31;
    int g = lane >> 2, tg = lane & 3;
    int p = blockIdx.x, b = p % NB, c = p / NB;
    const uint32_t* GHp = g_GPH + (size_t)b * NS2 * SPAD;
    const uint32_t* GLp = g_GPL + (size_t)b * NS2 * SPAD;
    const uint32_t* aHp = g_aPH + (size_t)p * NS2 * NT;
    const uint32_t* aLp = g_aPL + (size_t)p * NS2 * NT;
    int cap = caps[c];
    int capN = (cap + 7) >> 3;
    int bsegs = 2 * capN;

    float w2acc[16] = {};

    int pb = 0;
    load_stage(smb, GHp, GLp, aHp, aLp, 0, 0, bsegs, tid);

    for (int st = 0; st < 3; ++st) {
        int s_base = st * 128;
        float acc[8][4] = {};
        for (int kc = 0; kc < 6; ++kc) {
            int gi = st * 6 + kc;
            if (gi < 17) {
                int nst = (kc < 5) ? st : st + 1;
                int nkc = (kc < 5) ? kc + 1 : 0;
                load_stage(smb + (uint32_t)(pb ^ 1) * ST_SIZE,
                           GHp, GLp, aHp, aLp, nkc * 32, nst * 128, bsegs, tid);
                CPA_WAIT1();
            } else {
                CPA_WAIT0();
            }
            __syncthreads();
            uint32_t* base = (uint32_t*)(smc + (uint32_t)pb * ST_SIZE);
            uint32_t* cth = base;
            uint32_t* ctl = base + 4224;
            uint32_t* ath = base + 8448;
            uint32_t* atl = base + 10624;
            int arow = wid * 16 + g;
#pragma unroll
            for (int j = 0; j < 4; ++j) {
                int jb = j * 8;
                int r0 = (jb + tg) * 132 + arow;
                int r1 = (jb + tg + 4) * 132 + arow;
                uint32_t ah0 = cth[r0], ah1 = cth[r0 + 8];
                uint32_t ah2 = cth[r1], ah3 = cth[r1 + 8];
                uint32_t al0 = ctl[r0], al1 = ctl[r0 + 8];
                uint32_t al2 = ctl[r1], al3 = ctl[r1 + 8];
#pragma unroll
                for (int nt = 0; nt < 8; ++nt) {
                    if (nt < capN) {
                        int b0i = (jb + tg) * 68 + nt * 8 + g;
                        int b1i = (jb + tg + 4) * 68 + nt * 8 + g;
                        uint32_t bh0 = ath[b0i], bh1 = ath[b1i];
                        uint32_t bl0 = atl[b0i], bl1 = atl[b1i];
                        mma16(acc[nt], ah0, ah1, ah2, ah3, bh0, bh1);
                        mma16(acc[nt], ah0, ah1, ah2, ah3, bl0, bl1);
                        mma16(acc[nt], al0, al1, al2, al3, bh0, bh1);
                    }
                }
            }
            __syncthreads();
            pb ^= 1;
        }
        // contraction: w2[t] += a2u[s,t] * Y[s,t]; a2u = hi+lo from packed global
        int s0 = s_base + wid * 16 + g;
        int s1 = s0 + 8;
        int k20 = s0 >> 1, r0p = s0 & 1;
        int k21 = s1 >> 1, r1p = s1 & 1;
#pragma unroll
        for (int nt = 0; nt < 8; ++nt) {
            int col = nt * 8 + 2 * tg;
            uint32_t h, l;
            h = aHp[(size_t)k20 * NT + col];     l = aLp[(size_t)k20 * NT + col];
            float a00 = bfhalf(h, r0p) + bfhalf(l, r0p);
            h = aHp[(size_t)k20 * NT + col + 1]; l = aLp[(size_t)k20 * NT + col + 1];
            float a01 = bfhalf(h, r0p) + bfhalf(l, r0p);
            h = aHp[(size_t)k21 * NT + col];     l = aLp[(size_t)k21 * NT + col];
            float a10 = bfhalf(h, r1p) + bfhalf(l, r1p);
            h = aHp[(size_t)k21 * NT + col + 1]; l = aLp[(size_t)k21 * NT + col + 1];
            float a11 = bfhalf(h, r1p) + bfhalf(l, r1p);
            w2acc[nt * 2 + 0] += a00 * acc[nt][0] + a10 * acc[nt][2];
            w2acc[nt * 2 + 1] += a01 * acc[nt][1] + a11 * acc[nt][3];
        }
    }
#pragma unroll
    for (int i = 0; i < 16; ++i) {
        float v = w2acc[i];
        v += __shfl_xor_sync(0xffffffffu, v, 4);
        v += __shfl_xor_sync(0xffffffffu, v, 8);
        v += __shfl_xor_sync(0xffffffffu, v, 16);
        w2acc[i] = v;
    }
    __syncthreads();
    if (g == 0) {
#pragma unroll
        for (int i = 0; i < 16; ++i) {
            int col = (i >> 1) * 8 + 2 * tg + (i & 1);
            w2red[wid * 64 + col] = w2acc[i];
        }
    }
    __syncthreads();
    if (tid < 64) {
        float s = 0.f;
#pragma unroll
        for (int w = 0; w < 8; ++w) s += w2red[w * 64 + tid];
        g_w2[p * 64 + tid] = s;
    }
}

// ================= finalizers =================
__global__ void csim_kernel(const int* __restrict__ caps) {
    int p = blockIdx.x, b = p % NB, c = p / NB;
    int t = threadIdx.x;
    float cs = g_cols[p * 64 + t];
    float ci = 1.f / cs;
    float w12 = g_w12[p * 64 + t] * ci;
    float w2 = ci * sqrtf(fmaxf(g_w2[p * 64 + t], 0.f));
    float w1 = g_w1n[c * 64 + t];
    float sim = w12 / fmaxf(w1 * w2, EPSV);
    float row = (t < caps[c]) ? __expf(TEMP2 * sim) : 0.f;
#pragma unroll
    for (int o = 16; o; o >>= 1) row += __shfl_xor_sync(0xffffffffu, row, o);
    __shared__ float sred[2];
    if ((t & 31) == 0) sred[t >> 5] = row;
    __syncthreads();
    if (t == 0) g_sims[b * NB + c] = TEMP3 * logf(sred[0] + sred[1]);
}

__global__ void att_kernel(float* __restrict__ ao) {
    int b = blockIdx.x;
    int p = b * NB + b;
    int tid = threadIdx.x;
    __shared__ float ci[64];
    if (tid < 64) ci[tid] = 1.f / g_cols[p * 64 + tid];
    __syncthreads();
    const float* au = g_a2uD + (size_t)b * SPAD * NT;
    for (int i = tid; i < NS * NT; i += 256) {
        int s = i >> 6, t = i & 63;
        ao[((size_t)b * NT + t) * NS + s] = au[(size_t)s * NT + t] * ci[t];
    }
}

__global__ void loss_kernel(float* __restrict__ out) {
    __shared__ float part[4][NB];
    int i = threadIdx.x;
    if (i < NB) {
        const float* Ms = g_sims;
        const float* Mg = g_sc0;
        float m, sum;
        m = -INFINITY;
        for (int j = 0; j < NB; ++j) m = fmaxf(m, Ms[i * NB + j]);
        sum = 0.f;
        for (int j = 0; j < NB; ++j) sum += expf(Ms[i * NB + j] - m);
        part[0][i] = m + logf(sum) - Ms[i * NB + i];
        m = -INFINITY;
        for (int j = 0; j < NB; ++j) m = fmaxf(m, Ms[j * NB + i]);
        sum = 0.f;
        for (int j = 0; j < NB; ++j) sum += expf(Ms[j * NB + i] - m);
        part[1][i] = m + logf(sum) - Ms[i * NB + i];
        m = -INFINITY;
        for (int j = 0; j < NB; ++j) m = fmaxf(m, Mg[i * NB + j]);
        sum = 0.f;
        for (int j = 0; j < NB; ++j) sum += expf(Mg[i * NB + j] - m);
        part[2][i] = m + logf(sum) - Mg[i * NB + i];
        m = -INFINITY;
        for (int j = 0; j < NB; ++j) m = fmaxf(m, Mg[j * NB + i]);
        sum = 0.f;
        for (int j = 0; j < NB; ++j) sum += expf(Mg[j * NB + i] - m);
        part[3][i] = m + logf(sum) - Mg[i * NB + i];
    }
    __syncthreads();
    if (i == 0) {
        float l = 0.f;
        for (int k = 0; k < 4; ++k) {
            float s = 0.f;
            for (int j = 0; j < NB; ++j) s += part[k][j];
            l += s * (1.f / (float)NB);
        }
        out[0] = l;
    }
}

// ================= launch =================
extern "C" void kernel_launch(void* const* d_in, const int* in_sizes, int n_in,
                              void* d_out, int out_size) {
    const float* gfeat  = (const float*)d_in[0];
    const float* localf = (const float*)d_in[1];
    const float* words  = (const float*)d_in[2];
    const float* sfeat  = (const float*)d_in[3];
    const int*   caps   = (const int*)d_in[4];
    float* out = (float*)d_out;

    cudaFuncSetAttribute(scoreA_kernel, cudaFuncAttributeMaxDynamicSharedMemorySize, A_SMEM);
    cudaFuncSetAttribute(w2B_kernel, cudaFuncAttributeMaxDynamicSharedMemorySize, B_SMEM);

    size_t n_pad = (size_t)NB * NC * SPAD;
    size_t n_cw = (size_t)NB * ND2 * SPAD + (size_t)NB * ND2 * NT;
    pad_kernel<<<(unsigned)((n_pad + 255) / 256), 256>>>(localf);      // launch 1
    gram_kernel<<<dim3(6, NB), 256>>>();                               // launch 2
    prep_cw<<<(unsigned)((n_cw + 255) / 256), 256>>>(localf, words);   // launch 3
    scoreA_kernel<<<NPAIR, 256, A_SMEM>>>(caps);                       // launch 4 (ncu)
    w2B_kernel<<<NPAIR, 256, B_SMEM>>>(caps);                          // launch 5

    norms_kernel<<<NB, 64>>>(words, gfeat, sfeat);
    gscore_kernel<<<NB, 256>>>(gfeat, sfeat);
    csim_kernel<<<NPAIR, 64>>>(caps);

    int wa = (out_size >= 1 + NB * NT * NS) ? 1 : 0;
    if (wa) att_kernel<<<NB, 256>>>(out + 1);
    loss_kernel<<<1, 64>>>(out);
}